// round 14
// baseline (speedup 1.0000x reference)
#include <cuda_runtime.h>
#include <cuda_bf16.h>
#include <math.h>
#include <stdint.h>

#define N_SEQ  4096
#define SIZE_K 8192
#define HALF_K 4096

#define BM   128
#define BN   128
#define BKC  64          // K elements per pipeline chunk (128 bytes bf16)
#define GT   256         // threads per GEMM CTA (8 warps)

// ---------------- scratch (static device globals; no runtime alloc) ----------
__device__ __nv_bfloat16 g_xh[(size_t)N_SEQ * SIZE_K];
__device__ __nv_bfloat16 g_xl[(size_t)N_SEQ * SIZE_K];
__device__ __nv_bfloat16 g_wkh[(size_t)HALF_K * SIZE_K];   // Wk^T hi  [4096,8192]
__device__ __nv_bfloat16 g_wkl[(size_t)HALF_K * SIZE_K];
__device__ __nv_bfloat16 g_wvh[(size_t)HALF_K * SIZE_K];
__device__ __nv_bfloat16 g_wvl[(size_t)HALF_K * SIZE_K];
__device__ __nv_bfloat16 g_kh[(size_t)N_SEQ * HALF_K];     // K split
__device__ __nv_bfloat16 g_kl[(size_t)N_SEQ * HALF_K];
__device__ __nv_bfloat16 g_vh[(size_t)N_SEQ * HALF_K];     // V split
__device__ __nv_bfloat16 g_vl[(size_t)N_SEQ * HALF_K];
__device__ float         g_v [(size_t)N_SEQ * HALF_K];     // V fp32
__device__ float         g_s [(size_t)N_SEQ * N_SEQ];      // scores fp32

// ---------------- PTX helpers (base sm_103 features only) --------------------
static __device__ __forceinline__ uint32_t smem_u32(const void* p) {
    uint32_t a;
    asm("{ .reg .u64 t; cvta.to.shared.u64 t, %1; cvt.u32.u64 %0, t; }" : "=r"(a) : "l"(p));
    return a;
}
static __device__ __forceinline__ void cp16(uint32_t s, const void* g) {
    asm volatile("cp.async.cg.shared.global [%0], [%1], 16;" :: "r"(s), "l"(g));
}
static __device__ __forceinline__ void cp_commit() {
    asm volatile("cp.async.commit_group;" ::: "memory");
}
template<int NP> static __device__ __forceinline__ void cp_wait() {
    asm volatile("cp.async.wait_group %0;" :: "n"(NP) : "memory");
}
static __device__ __forceinline__ void ldsm4(uint32_t* r, uint32_t addr) {
    asm volatile("ldmatrix.sync.aligned.m8n8.x4.shared.b16 {%0,%1,%2,%3}, [%4];"
        : "=r"(r[0]), "=r"(r[1]), "=r"(r[2]), "=r"(r[3]) : "r"(addr));
}
static __device__ __forceinline__ void mma16816(float* c, const uint32_t* a, const uint32_t* b) {
    asm volatile(
        "mma.sync.aligned.m16n8k16.row.col.f32.bf16.bf16.f32 "
        "{%0,%1,%2,%3}, {%4,%5,%6,%7}, {%8,%9}, {%0,%1,%2,%3};"
        : "+f"(c[0]), "+f"(c[1]), "+f"(c[2]), "+f"(c[3])
        : "r"(a[0]), "r"(a[1]), "r"(a[2]), "r"(a[3]), "r"(b[0]), "r"(b[1]));
}
static __device__ __forceinline__ void split2(float x0, float x1, uint32_t& h, uint32_t& l) {
    __nv_bfloat16 h0 = __float2bfloat16(x0), h1 = __float2bfloat16(x1);
    __nv_bfloat16 l0 = __float2bfloat16(x0 - __bfloat162float(h0));
    __nv_bfloat16 l1 = __float2bfloat16(x1 - __bfloat162float(h1));
    h = (uint32_t)__bfloat16_as_ushort(h0) | ((uint32_t)__bfloat16_as_ushort(h1) << 16);
    l = (uint32_t)__bfloat16_as_ushort(l0) | ((uint32_t)__bfloat16_as_ushort(l1) << 16);
}

// ---------------- convert / split kernels ------------------------------------
__global__ __launch_bounds__(256)
void convert_x_kernel(const float* __restrict__ x)
{
    const size_t total4 = (size_t)N_SEQ * SIZE_K / 4;
    __nv_bfloat162* xh2 = reinterpret_cast<__nv_bfloat162*>(g_xh);
    __nv_bfloat162* xl2 = reinterpret_cast<__nv_bfloat162*>(g_xl);
    for (size_t i = (size_t)blockIdx.x * blockDim.x + threadIdx.x; i < total4;
         i += (size_t)gridDim.x * blockDim.x) {
        float4 v = reinterpret_cast<const float4*>(x)[i];
        __nv_bfloat16 h0 = __float2bfloat16(v.x), h1 = __float2bfloat16(v.y);
        __nv_bfloat16 h2 = __float2bfloat16(v.z), h3 = __float2bfloat16(v.w);
        __nv_bfloat16 l0 = __float2bfloat16(v.x - __bfloat162float(h0));
        __nv_bfloat16 l1 = __float2bfloat16(v.y - __bfloat162float(h1));
        __nv_bfloat16 l2 = __float2bfloat16(v.z - __bfloat162float(h2));
        __nv_bfloat16 l3 = __float2bfloat16(v.w - __bfloat162float(h3));
        xh2[2 * i]     = __nv_bfloat162(h0, h1);
        xh2[2 * i + 1] = __nv_bfloat162(h2, h3);
        xl2[2 * i]     = __nv_bfloat162(l0, l1);
        xl2[2 * i + 1] = __nv_bfloat162(l2, l3);
    }
}

// W [SIZE_K, HALF_K] fp32 -> WT hi/lo [HALF_K, SIZE_K] bf16
template<int WSEL>
__global__ __launch_bounds__(256)
void transpose_split_kernel(const float* __restrict__ W)
{
    __nv_bfloat16* dh = (WSEL == 0) ? g_wkh : g_wvh;
    __nv_bfloat16* dl = (WSEL == 0) ? g_wkl : g_wvl;
    __shared__ float t[32][33];
    int n0 = blockIdx.x * 32;
    int k0 = blockIdx.y * 32;
    int tx = threadIdx.x, ty = threadIdx.y;   // block (32, 8)
    #pragma unroll
    for (int i = 0; i < 4; i++)
        t[ty + i * 8][tx] = W[(size_t)(k0 + ty + i * 8) * HALF_K + n0 + tx];
    __syncthreads();
    #pragma unroll
    for (int i = 0; i < 4; i++) {
        int n = n0 + ty + i * 8;
        int k = k0 + tx;
        float v = t[tx][ty + i * 8];
        __nv_bfloat16 h = __float2bfloat16(v);
        __nv_bfloat16 l = __float2bfloat16(v - __bfloat162float(h));
        dh[(size_t)n * SIZE_K + k] = h;
        dl[(size_t)n * SIZE_K + k] = l;
    }
}

// ---------------- HMMA split-bf16 GEMM, A-lo via LDG -------------------------
// MODE 0: K proj  (A=x, B=Wk^T, out: g_kh/g_kl,     bias=bk, K=8192)
// MODE 1: V proj  (A=x, B=Wv^T, out: g_v,g_vh/g_vl, bias=bv, K=8192)
// MODE 2: scores  (A=V, B=K,    out: g_s,           alpha=1/90, K=4096)
//
// smem stage (48 KB): Ah[128][128B] | Bh[128][128B] | Bl[128][128B].
// A-lo fragments are loaded per-lane from gmem (L1-cached), 1-step lookahead.
#define STG_BYTES 49152u
#define OBH 16384u
#define OBL 32768u
#define NSTG 3
#define SMEM_BYTES (NSTG * STG_BYTES)

template<int MODE>
__global__ __launch_bounds__(GT, 1)
void gemm3_kernel(const float* __restrict__ bias)
{
    const __nv_bfloat16 *Ah, *Al, *Bh, *Bl;
    int Ktot;
    if (MODE == 0)      { Ah = g_xh; Al = g_xl; Bh = g_wkh; Bl = g_wkl; Ktot = SIZE_K; }
    else if (MODE == 1) { Ah = g_xh; Al = g_xl; Bh = g_wvh; Bl = g_wvl; Ktot = SIZE_K; }
    else                { Ah = g_vh; Al = g_vl; Bh = g_kh;  Bl = g_kl;  Ktot = HALF_K; }

    extern __shared__ char smem[];
    const uint32_t sb = smem_u32(smem);
    const int tid  = threadIdx.x;
    const int wid  = tid >> 5;
    const int lane = tid & 31;
    const int wm   = wid & 3;     // warp row 0..3  (32 rows each)
    const int wn   = wid >> 2;    // warp col 0..1  (64 cols each)

    const int bm = blockIdx.x * BM;
    const int bn = blockIdx.y * BN;

    float acc[2][8][4];
    #pragma unroll
    for (int t = 0; t < 2; t++)
        #pragma unroll
        for (int n = 0; n < 8; n++)
            #pragma unroll
            for (int q = 0; q < 4; q++) acc[t][n][q] = 0.0f;

    const int nch = Ktot / BKC;

    auto load_chunk = [&](int ch) {
        const uint32_t stg = sb + (uint32_t)(ch % NSTG) * STG_BYTES;
        const size_t k0 = (size_t)ch * BKC;
        #pragma unroll
        for (int i = 0; i < 4; i++) {
            int pos = tid + i * GT;            // 0..1023
            int row = pos >> 3, seg = pos & 7;
            uint32_t soff = row * 128 + ((seg ^ (row & 7)) << 4);
            size_t ga = (size_t)(bm + row) * Ktot + k0 + seg * 8;
            size_t gb = (size_t)(bn + row) * Ktot + k0 + seg * 8;
            cp16(stg +       soff, Ah + ga);
            cp16(stg + OBH + soff, Bh + gb);
            cp16(stg + OBL + soff, Bl + gb);
        }
    };

    // A-lo per-lane gmem fragment base: rows (bm + wm*32 + g [+8/+16/+24]), col pair (lane&3)*2
    const size_t sK = (size_t)Ktot;
    const __nv_bfloat16* AlBase =
        Al + (size_t)(bm + wm * 32 + (lane >> 2)) * sK + (lane & 3) * 2;

    uint32_t aflb[2][2][4];   // [buf][t][reg], one-k16-step lookahead
    auto ldg_afl = [&](uint32_t b[2][4], int kg) {
        #pragma unroll
        for (int t = 0; t < 2; ++t) {
            const __nv_bfloat16* p = AlBase + (size_t)(t * 16) * sK + kg;
            b[t][0] = __ldg((const uint32_t*)(p));
            b[t][1] = __ldg((const uint32_t*)(p + 8 * sK));
            b[t][2] = __ldg((const uint32_t*)(p + 8));
            b[t][3] = __ldg((const uint32_t*)(p + 8 * sK + 8));
        }
    };

    // prologue: stage 2 chunks, prefetch first A-lo fragments
    load_chunk(0); cp_commit();
    if (nch > 1) load_chunk(1);
    cp_commit();
    ldg_afl(aflb[0], 0);
    int pb = 0;
    int kg = 0;
    const int kg_last = Ktot - 16;

    for (int ch = 0; ch < nch; ++ch) {
        cp_wait<1>();            // chunk ch resident
        __syncthreads();         // all warps done reading stage (ch+2)%NSTG
        if (ch + 2 < nch) load_chunk(ch + 2);
        cp_commit();             // always commit (possibly empty) to keep counts

        const uint32_t stg = sb + (uint32_t)(ch % NSTG) * STG_BYTES;

        #pragma unroll
        for (int k16 = 0; k16 < 4; ++k16) {
            // prefetch A-lo for next k16 step (cross-chunk too)
            const int nxt = pb ^ 1;
            int kg_next = kg + 16;
            if (kg_next > kg_last) kg_next = kg_last;   // tail clamp (values unused)
            ldg_afl(aflb[nxt], kg_next);

            uint32_t afh[2][4], bfh[4][4], bfl[4][4];
            #pragma unroll
            for (int t = 0; t < 2; ++t) {
                int row = wm * 32 + t * 16 + (lane & 15);
                int seg = k16 * 2 + (lane >> 4);
                uint32_t off = row * 128 + ((seg ^ (row & 7)) << 4);
                ldsm4(afh[t], stg + off);
            }
            #pragma unroll
            for (int p = 0; p < 4; ++p) {
                int row = wn * 64 + p * 16 + ((lane >> 4) << 3) + (lane & 7);
                int seg = k16 * 2 + ((lane >> 3) & 1);
                uint32_t off = row * 128 + ((seg ^ (row & 7)) << 4);
                ldsm4(bfh[p], stg + OBH + off);
                ldsm4(bfl[p], stg + OBL + off);
            }
            // hh
            #pragma unroll
            for (int t = 0; t < 2; ++t)
                #pragma unroll
                for (int nt = 0; nt < 8; ++nt)
                    mma16816(acc[t][nt], afh[t], &bfh[nt >> 1][(nt & 1) * 2]);
            // hl
            #pragma unroll
            for (int t = 0; t < 2; ++t)
                #pragma unroll
                for (int nt = 0; nt < 8; ++nt)
                    mma16816(acc[t][nt], afh[t], &bfl[nt >> 1][(nt & 1) * 2]);
            // lh (A-lo from gmem-loaded fragments)
            #pragma unroll
            for (int t = 0; t < 2; ++t)
                #pragma unroll
                for (int nt = 0; nt < 8; ++nt)
                    mma16816(acc[t][nt], aflb[pb][t], &bfh[nt >> 1][(nt & 1) * 2]);

            pb ^= 1;
            kg += 16;
        }
    }

    // ---- epilogue: mma C frag: c0,c1 @ (row, col..col+1), c2,c3 @ (row+8)
    #pragma unroll
    for (int t = 0; t < 2; ++t) {
        #pragma unroll
        for (int nt = 0; nt < 8; ++nt) {
            float* c = acc[t][nt];
            const int n  = bn + wn * 64 + nt * 8 + (lane & 3) * 2;
            const int m0 = bm + wm * 32 + t * 16 + (lane >> 2);
            if (MODE == 2) {
                const float a = 1.0f / 90.0f;
                *(float2*)&g_s[(size_t)m0 * N_SEQ + n]       = make_float2(c[0] * a, c[1] * a);
                *(float2*)&g_s[(size_t)(m0 + 8) * N_SEQ + n] = make_float2(c[2] * a, c[3] * a);
            } else {
                float b0 = __ldg(&bias[n]), b1 = __ldg(&bias[n + 1]);
                float x0 = c[0] + b0, x1 = c[1] + b1;
                float y0 = c[2] + b0, y1 = c[3] + b1;
                if (MODE == 1) {
                    *(float2*)&g_v[(size_t)m0 * HALF_K + n]       = make_float2(x0, x1);
                    *(float2*)&g_v[(size_t)(m0 + 8) * HALF_K + n] = make_float2(y0, y1);
                }
                __nv_bfloat16* dsth = (MODE == 0) ? g_kh : g_vh;
                __nv_bfloat16* dstl = (MODE == 0) ? g_kl : g_vl;
                uint32_t h, l;
                split2(x0, x1, h, l);
                *(uint32_t*)&dsth[(size_t)m0 * HALF_K + n] = h;
                *(uint32_t*)&dstl[(size_t)m0 * HALF_K + n] = l;
                split2(y0, y1, h, l);
                *(uint32_t*)&dsth[(size_t)(m0 + 8) * HALF_K + n] = h;
                *(uint32_t*)&dstl[(size_t)(m0 + 8) * HALF_K + n] = l;
            }
        }
    }
}

// ---------------- fast exp on the FMA pipe (no MUFU) -------------------------
__device__ __forceinline__ float fast_exp(float x) {
    x = fmaxf(x, -87.0f);
    const float L2E = 1.4426950408889634f;
    float t = x * L2E;
    float z = t + 12582912.0f;
    float n = z - 12582912.0f;
    float f = t - n;
    int   i = __float_as_int(z) - 0x4B400000;
    float p = 1.3333558146e-3f;
    p = fmaf(p, f, 9.6181291076e-3f);
    p = fmaf(p, f, 5.5504108665e-2f);
    p = fmaf(p, f, 2.4022650696e-1f);
    p = fmaf(p, f, 6.9314718056e-1f);
    p = fmaf(p, f, 1.0f);
    float sc = __int_as_float((i + 127) << 23);
    return p * sc;
}

__device__ __forceinline__ void combine(float& m, float& Z, float& c, int& bi,
                                        float m2, float Z2, float c2, int bi2) {
    float M  = fmaxf(m, m2);
    float r1 = fast_exp(m  - M);
    float r2 = fast_exp(m2 - M);
    Z = Z * r1 + Z2 * r2;
    float ca = c  * r1;
    float cb = c2 * r2;
    if (cb > ca || (cb == ca && bi2 < bi)) { c = cb; bi = bi2; }
    else                                   { c = ca; }
    m = M;
}

__global__ __launch_bounds__(256)
void softmax_combine_kernel(float* __restrict__ out)
{
    const int row = blockIdx.x;
    const float4* __restrict__ S4 = (const float4*)(g_s + (size_t)row * N_SEQ);
    const float4* __restrict__ V4 = (const float4*)(g_v + (size_t)row * N_SEQ);
    const int tid = threadIdx.x;

    float m = -INFINITY, Z = 0.0f, c = -INFINITY;
    int bi = 0;

    #pragma unroll
    for (int it = 0; it < 4; it++) {
        int q = tid + it * 256;
        float4 s4 = S4[q];
        float4 v4 = V4[q];
        float ss[4] = {s4.x, s4.y, s4.z, s4.w};
        float vv[4] = {v4.x, v4.y, v4.z, v4.w};
        #pragma unroll
        for (int l = 0; l < 4; l++) {
            float s = ss[l];
            int   j = q * 4 + l;
            if (s > m) {
                float r = fast_exp(m - s);
                Z = Z * r + 1.0f;
                c = c * r;
                float cand = vv[l];
                if (cand > c || (cand == c && j < bi)) { c = cand; bi = j; }
                m = s;
            } else {
                float e = fast_exp(s - m);
                Z += e;
                float cand = e * vv[l];
                if (cand > c || (cand == c && j < bi)) { c = cand; bi = j; }
            }
        }
    }

    const unsigned full = 0xffffffffu;
    #pragma unroll
    for (int off = 16; off > 0; off >>= 1) {
        float m2 = __shfl_down_sync(full, m, off);
        float Z2 = __shfl_down_sync(full, Z, off);
        float c2 = __shfl_down_sync(full, c, off);
        int   b2 = __shfl_down_sync(full, bi, off);
        combine(m, Z, c, bi, m2, Z2, c2, b2);
    }

    __shared__ float sm[8], sz[8], sc[8];
    __shared__ int   sbuf[8];
    int wid = tid >> 5, lane = tid & 31;
    if (lane == 0) { sm[wid] = m; sz[wid] = Z; sc[wid] = c; sbuf[wid] = bi; }
    __syncthreads();
    if (tid == 0) {
        #pragma unroll
        for (int w = 1; w < 8; w++)
            combine(m, Z, c, bi, sm[w], sz[w], sc[w], sbuf[w]);
        out[row]         = c / Z;
        out[N_SEQ + row] = (float)bi;
    }
}

// ---------------- launch ------------------------------------------------------
extern "C" void kernel_launch(void* const* d_in, const int* in_sizes, int n_in,
                              void* d_out, int out_size)
{
    const float* x  = (const float*)d_in[0];
    const float* Wk = (const float*)d_in[1];
    const float* bk = (const float*)d_in[2];
    const float* Wv = (const float*)d_in[3];
    const float* bv = (const float*)d_in[4];
    // d_in[5]/d_in[6] (Wq,bq) are dead in the reference (x_q = x@Wv+bv)
    float* out = (float*)d_out;

    static bool attr_done = false;
    if (!attr_done) {
        cudaFuncSetAttribute(gemm3_kernel<0>, cudaFuncAttributeMaxDynamicSharedMemorySize, SMEM_BYTES);
        cudaFuncSetAttribute(gemm3_kernel<1>, cudaFuncAttributeMaxDynamicSharedMemorySize, SMEM_BYTES);
        cudaFuncSetAttribute(gemm3_kernel<2>, cudaFuncAttributeMaxDynamicSharedMemorySize, SMEM_BYTES);
        attr_done = true;
    }

    // 1) split x into bf16 hi/lo
    convert_x_kernel<<<8192, 256>>>(x);
    // 2) transpose+split weights
    dim3 tg(HALF_K / 32, SIZE_K / 32);
    transpose_split_kernel<0><<<tg, dim3(32, 8)>>>(Wk);
    transpose_split_kernel<1><<<tg, dim3(32, 8)>>>(Wv);
    // 3) projections + scores on HMMA tensor cores (3-term bf16 split, A-lo via LDG)
    dim3 gproj(N_SEQ / BM, HALF_K / BN);
    dim3 gsc  (N_SEQ / BM, N_SEQ / BN);
    gemm3_kernel<0><<<gproj, GT, SMEM_BYTES>>>(bk);
    gemm3_kernel<1><<<gproj, GT, SMEM_BYTES>>>(bv);
    gemm3_kernel<2><<<gsc,   GT, SMEM_BYTES>>>(nullptr);
    // 4) softmax + elementwise V + row max/argmax
    softmax_combine_kernel<<<N_SEQ, 256>>>(out);
}

// round 15
// speedup vs baseline: 1.0556x; 1.0556x over previous
#include <cuda_runtime.h>
#include <cuda_bf16.h>
#include <math.h>
#include <stdint.h>

#define N_SEQ  4096
#define SIZE_K 8192
#define HALF_K 4096
#define GT   256         // threads per GEMM CTA (8 warps)

// ---------------- scratch (static device globals; no runtime alloc) ----------
__device__ __nv_bfloat16 g_xh[(size_t)N_SEQ * SIZE_K];
__device__ __nv_bfloat16 g_xl[(size_t)N_SEQ * SIZE_K];
__device__ __nv_bfloat16 g_wkh[(size_t)HALF_K * SIZE_K];   // Wk^T hi  [4096,8192]
__device__ __nv_bfloat16 g_wkl[(size_t)HALF_K * SIZE_K];
__device__ __nv_bfloat16 g_wvh[(size_t)HALF_K * SIZE_K];
__device__ __nv_bfloat16 g_wvl[(size_t)HALF_K * SIZE_K];
__device__ __nv_bfloat16 g_kh[(size_t)N_SEQ * HALF_K];     // K split
__device__ __nv_bfloat16 g_kl[(size_t)N_SEQ * HALF_K];
__device__ __nv_bfloat16 g_vh[(size_t)N_SEQ * HALF_K];     // V split
__device__ __nv_bfloat16 g_vl[(size_t)N_SEQ * HALF_K];
__device__ float         g_k [(size_t)N_SEQ * HALF_K];     // K fp32 partial
__device__ float         g_v [(size_t)N_SEQ * HALF_K];     // V fp32 partial/final
__device__ float         g_s [(size_t)N_SEQ * N_SEQ];      // scores partial/final

// ---------------- PTX helpers (base sm_103 features only) --------------------
static __device__ __forceinline__ uint32_t smem_u32(const void* p) {
    uint32_t a;
    asm("{ .reg .u64 t; cvta.to.shared.u64 t, %1; cvt.u32.u64 %0, t; }" : "=r"(a) : "l"(p));
    return a;
}
static __device__ __forceinline__ void cp16(uint32_t s, const void* g) {
    asm volatile("cp.async.cg.shared.global [%0], [%1], 16;" :: "r"(s), "l"(g));
}
static __device__ __forceinline__ void cp_commit() {
    asm volatile("cp.async.commit_group;" ::: "memory");
}
template<int NP> static __device__ __forceinline__ void cp_wait() {
    asm volatile("cp.async.wait_group %0;" :: "n"(NP) : "memory");
}
static __device__ __forceinline__ void ldsm4(uint32_t* r, uint32_t addr) {
    asm volatile("ldmatrix.sync.aligned.m8n8.x4.shared.b16 {%0,%1,%2,%3}, [%4];"
        : "=r"(r[0]), "=r"(r[1]), "=r"(r[2]), "=r"(r[3]) : "r"(addr));
}
static __device__ __forceinline__ void mma16816(float* c, const uint32_t* a, const uint32_t* b) {
    asm volatile(
        "mma.sync.aligned.m16n8k16.row.col.f32.bf16.bf16.f32 "
        "{%0,%1,%2,%3}, {%4,%5,%6,%7}, {%8,%9}, {%0,%1,%2,%3};"
        : "+f"(c[0]), "+f"(c[1]), "+f"(c[2]), "+f"(c[3])
        : "r"(a[0]), "r"(a[1]), "r"(a[2]), "r"(a[3]), "r"(b[0]), "r"(b[1]));
}
static __device__ __forceinline__ void split2(float x0, float x1, uint32_t& h, uint32_t& l) {
    __nv_bfloat16 h0 = __float2bfloat16(x0), h1 = __float2bfloat16(x1);
    __nv_bfloat16 l0 = __float2bfloat16(x0 - __bfloat162float(h0));
    __nv_bfloat16 l1 = __float2bfloat16(x1 - __bfloat162float(h1));
    h = (uint32_t)__bfloat16_as_ushort(h0) | ((uint32_t)__bfloat16_as_ushort(h1) << 16);
    l = (uint32_t)__bfloat16_as_ushort(l0) | ((uint32_t)__bfloat16_as_ushort(l1) << 16);
}

// ---------------- convert / split kernels ------------------------------------
__global__ __launch_bounds__(256)
void convert_x_kernel(const float* __restrict__ x)
{
    const size_t total4 = (size_t)N_SEQ * SIZE_K / 4;
    __nv_bfloat162* xh2 = reinterpret_cast<__nv_bfloat162*>(g_xh);
    __nv_bfloat162* xl2 = reinterpret_cast<__nv_bfloat162*>(g_xl);
    for (size_t i = (size_t)blockIdx.x * blockDim.x + threadIdx.x; i < total4;
         i += (size_t)gridDim.x * blockDim.x) {
        float4 v = reinterpret_cast<const float4*>(x)[i];
        __nv_bfloat16 h0 = __float2bfloat16(v.x), h1 = __float2bfloat16(v.y);
        __nv_bfloat16 h2 = __float2bfloat16(v.z), h3 = __float2bfloat16(v.w);
        __nv_bfloat16 l0 = __float2bfloat16(v.x - __bfloat162float(h0));
        __nv_bfloat16 l1 = __float2bfloat16(v.y - __bfloat162float(h1));
        __nv_bfloat16 l2 = __float2bfloat16(v.z - __bfloat162float(h2));
        __nv_bfloat16 l3 = __float2bfloat16(v.w - __bfloat162float(h3));
        xh2[2 * i]     = __nv_bfloat162(h0, h1);
        xh2[2 * i + 1] = __nv_bfloat162(h2, h3);
        xl2[2 * i]     = __nv_bfloat162(l0, l1);
        xl2[2 * i + 1] = __nv_bfloat162(l2, l3);
    }
}

// W [SIZE_K, HALF_K] fp32 -> WT hi/lo [HALF_K, SIZE_K] bf16
template<int WSEL>
__global__ __launch_bounds__(256)
void transpose_split_kernel(const float* __restrict__ W)
{
    __nv_bfloat16* dh = (WSEL == 0) ? g_wkh : g_wvh;
    __nv_bfloat16* dl = (WSEL == 0) ? g_wkl : g_wvl;
    __shared__ float t[32][33];
    int n0 = blockIdx.x * 32;
    int k0 = blockIdx.y * 32;
    int tx = threadIdx.x, ty = threadIdx.y;   // block (32, 8)
    #pragma unroll
    for (int i = 0; i < 4; i++)
        t[ty + i * 8][tx] = W[(size_t)(k0 + ty + i * 8) * HALF_K + n0 + tx];
    __syncthreads();
    #pragma unroll
    for (int i = 0; i < 4; i++) {
        int n = n0 + ty + i * 8;
        int k = k0 + tx;
        float v = t[tx][ty + i * 8];
        __nv_bfloat16 h = __float2bfloat16(v);
        __nv_bfloat16 l = __float2bfloat16(v - __bfloat162float(h));
        dh[(size_t)n * SIZE_K + k] = h;
        dl[(size_t)n * SIZE_K + k] = l;
    }
}

// ================= PASS 1: C = Ah*Bh^T + Al*Bh^T (hh + lh, share Bh) =========
// MODE 0: A=x, B=Wk_h  -> g_k        MODE 1: A=x, B=Wv_h -> g_v
// MODE 2: A=V, B=K_h   -> g_s (partial, unscaled)
// CTA 128x128, 8 warps 4x2, BKC=32, 3 stages x 24KB = 72KB, occ 2.
#define P1_STG 24576u
#define P1_BUF 8192u
#define P1_NSTG 3
#define P1_SMEM (P1_NSTG * P1_STG)

template<int MODE>
__global__ __launch_bounds__(GT, 2)
void gemm_p1_kernel()
{
    const __nv_bfloat16 *Ah, *Al, *Bh;
    int Ktot;
    if (MODE == 0)      { Ah = g_xh; Al = g_xl; Bh = g_wkh; Ktot = SIZE_K; }
    else if (MODE == 1) { Ah = g_xh; Al = g_xl; Bh = g_wvh; Ktot = SIZE_K; }
    else                { Ah = g_vh; Al = g_vl; Bh = g_kh;  Ktot = HALF_K; }
    float* C = (MODE == 0) ? g_k : ((MODE == 1) ? g_v : g_s);

    extern __shared__ char smem[];
    const uint32_t sb = smem_u32(smem);
    const int tid  = threadIdx.x;
    const int wid  = tid >> 5;
    const int lane = tid & 31;
    const int wm   = wid & 3;
    const int wn   = wid >> 2;

    const int bm = blockIdx.x * 128;
    const int bn = blockIdx.y * 128;

    float acc[2][8][4];
    #pragma unroll
    for (int t = 0; t < 2; t++)
        #pragma unroll
        for (int n = 0; n < 8; n++)
            #pragma unroll
            for (int q = 0; q < 4; q++) acc[t][n][q] = 0.0f;

    const int nch = Ktot / 32;

    auto load_chunk = [&](int ch) {
        const uint32_t stg = sb + (uint32_t)(ch % P1_NSTG) * P1_STG;
        const size_t k0 = (size_t)ch * 32;
        #pragma unroll
        for (int i = 0; i < 2; i++) {
            int pos = tid + i * GT;            // 0..511
            int row = pos >> 2, seg = pos & 3;
            uint32_t soff = row * 64 + ((seg ^ ((row >> 1) & 3)) << 4);
            size_t ga = (size_t)(bm + row) * Ktot + k0 + seg * 8;
            size_t gb = (size_t)(bn + row) * Ktot + k0 + seg * 8;
            cp16(stg +            soff, Ah + ga);
            cp16(stg +   P1_BUF + soff, Al + ga);
            cp16(stg + 2*P1_BUF + soff, Bh + gb);
        }
    };

    load_chunk(0); cp_commit();
    load_chunk(1); cp_commit();

    for (int ch = 0; ch < nch; ++ch) {
        cp_wait<1>();
        __syncthreads();
        if (ch + 2 < nch) load_chunk(ch + 2);
        cp_commit();

        const uint32_t stg = sb + (uint32_t)(ch % P1_NSTG) * P1_STG;

        #pragma unroll
        for (int k16 = 0; k16 < 2; ++k16) {
            uint32_t afh[2][4], afl[2][4], bfh[4][4];
            #pragma unroll
            for (int t = 0; t < 2; ++t) {
                int row = wm * 32 + t * 16 + (lane & 15);
                int seg = k16 * 2 + (lane >> 4);
                uint32_t off = row * 64 + ((seg ^ ((row >> 1) & 3)) << 4);
                ldsm4(afh[t], stg + off);
                ldsm4(afl[t], stg + P1_BUF + off);
            }
            #pragma unroll
            for (int p = 0; p < 4; ++p) {
                int row = wn * 64 + p * 16 + ((lane >> 4) << 3) + (lane & 7);
                int seg = k16 * 2 + ((lane >> 3) & 1);
                uint32_t off = row * 64 + ((seg ^ ((row >> 1) & 3)) << 4);
                ldsm4(bfh[p], stg + 2*P1_BUF + off);
            }
            // hh
            #pragma unroll
            for (int t = 0; t < 2; ++t)
                #pragma unroll
                for (int nt = 0; nt < 8; ++nt)
                    mma16816(acc[t][nt], afh[t], &bfh[nt >> 1][(nt & 1) * 2]);
            // lh
            #pragma unroll
            for (int t = 0; t < 2; ++t)
                #pragma unroll
                for (int nt = 0; nt < 8; ++nt)
                    mma16816(acc[t][nt], afl[t], &bfh[nt >> 1][(nt & 1) * 2]);
        }
    }

    // write fp32 partial (row stride 4096 for all modes)
    #pragma unroll
    for (int t = 0; t < 2; ++t) {
        #pragma unroll
        for (int nt = 0; nt < 8; ++nt) {
            float* c = acc[t][nt];
            const int n  = bn + wn * 64 + nt * 8 + (lane & 3) * 2;
            const int m0 = bm + wm * 32 + t * 16 + (lane >> 2);
            *(float2*)&C[(size_t)m0 * 4096 + n]       = make_float2(c[0], c[1]);
            *(float2*)&C[(size_t)(m0 + 8) * 4096 + n] = make_float2(c[2], c[3]);
        }
    }
}

// ================= PASS 2: C += Ah*Bl^T (hl) + epilogue ======================
// MODE 0: A=x_h, B=Wk_l; out g_kh/g_kl (+bias bk)
// MODE 1: A=x_h, B=Wv_l; out g_v fp32 + g_vh/g_vl (+bias bv)
// MODE 2: A=V_h, B=K_l;  out g_s final (x 1/90)
// CTA 128x256, 8 warps (4 rows x 2 cols), warp tile 32x128. BKC=32.
#define P2_STG 24576u
#define P2_OB  8192u
#define P2_NSTG 3
#define P2_SMEM (P2_NSTG * P2_STG)

template<int MODE>
__global__ __launch_bounds__(GT, 1)
void gemm_p2_kernel(const float* __restrict__ bias)
{
    const __nv_bfloat16 *A, *B;
    int Ktot;
    if (MODE == 0)      { A = g_xh; B = g_wkl; Ktot = SIZE_K; }
    else if (MODE == 1) { A = g_xh; B = g_wvl; Ktot = SIZE_K; }
    else                { A = g_vh; B = g_kl;  Ktot = HALF_K; }
    float* C = (MODE == 0) ? g_k : ((MODE == 1) ? g_v : g_s);

    extern __shared__ char smem[];
    const uint32_t sb = smem_u32(smem);
    const int tid  = threadIdx.x;
    const int wid  = tid >> 5;
    const int lane = tid & 31;
    const int wm   = wid & 3;     // 4 warp rows of 32
    const int wn   = wid >> 2;    // 2 warp cols of 128

    const int bm = blockIdx.x * 128;
    const int bn = blockIdx.y * 256;

    float acc[2][16][4];
    #pragma unroll
    for (int t = 0; t < 2; t++)
        #pragma unroll
        for (int n = 0; n < 16; n++)
            #pragma unroll
            for (int q = 0; q < 4; q++) acc[t][n][q] = 0.0f;

    const int nch = Ktot / 32;

    auto load_chunk = [&](int ch) {
        const uint32_t stg = sb + (uint32_t)(ch % P2_NSTG) * P2_STG;
        const size_t k0 = (size_t)ch * 32;
        #pragma unroll
        for (int i = 0; i < 2; i++) {
            int pos = tid + i * GT;            // 0..511 (A: 128 rows)
            int row = pos >> 2, seg = pos & 3;
            uint32_t soff = row * 64 + ((seg ^ ((row >> 1) & 3)) << 4);
            cp16(stg + soff, A + (size_t)(bm + row) * Ktot + k0 + seg * 8);
        }
        #pragma unroll
        for (int i = 0; i < 4; i++) {
            int pos = tid + i * GT;            // 0..1023 (B: 256 rows)
            int row = pos >> 2, seg = pos & 3;
            uint32_t soff = row * 64 + ((seg ^ ((row >> 1) & 3)) << 4);
            cp16(stg + P2_OB + soff, B + (size_t)(bn + row) * Ktot + k0 + seg * 8);
        }
    };

    load_chunk(0); cp_commit();
    load_chunk(1); cp_commit();

    for (int ch = 0; ch < nch; ++ch) {
        cp_wait<1>();
        __syncthreads();
        if (ch + 2 < nch) load_chunk(ch + 2);
        cp_commit();

        const uint32_t stg = sb + (uint32_t)(ch % P2_NSTG) * P2_STG;

        #pragma unroll
        for (int k16 = 0; k16 < 2; ++k16) {
            uint32_t afh[2][4];
            #pragma unroll
            for (int t = 0; t < 2; ++t) {
                int row = wm * 32 + t * 16 + (lane & 15);
                int seg = k16 * 2 + (lane >> 4);
                uint32_t off = row * 64 + ((seg ^ ((row >> 1) & 3)) << 4);
                ldsm4(afh[t], stg + off);
            }
            #pragma unroll
            for (int p = 0; p < 8; ++p) {
                int row = wn * 128 + p * 16 + ((lane >> 4) << 3) + (lane & 7);
                int seg = k16 * 2 + ((lane >> 3) & 1);
                uint32_t off = row * 64 + ((seg ^ ((row >> 1) & 3)) << 4);
                uint32_t bf[4];
                ldsm4(bf, stg + P2_OB + off);
                #pragma unroll
                for (int t = 0; t < 2; ++t) {
                    mma16816(acc[t][2 * p],     afh[t], &bf[0]);
                    mma16816(acc[t][2 * p + 1], afh[t], &bf[2]);
                }
            }
        }
    }

    // ---- epilogue: C += acc, then bias/scale + outputs
    #pragma unroll
    for (int t = 0; t < 2; ++t) {
        #pragma unroll
        for (int nt = 0; nt < 16; ++nt) {
            float* c = acc[t][nt];
            const int n  = bn + wn * 128 + nt * 8 + (lane & 3) * 2;
            const int m0 = bm + wm * 32 + t * 16 + (lane >> 2);
            float2 p0 = *(float2*)&C[(size_t)m0 * 4096 + n];
            float2 p1 = *(float2*)&C[(size_t)(m0 + 8) * 4096 + n];
            if (MODE == 2) {
                const float a = 1.0f / 90.0f;
                *(float2*)&g_s[(size_t)m0 * N_SEQ + n] =
                    make_float2((p0.x + c[0]) * a, (p0.y + c[1]) * a);
                *(float2*)&g_s[(size_t)(m0 + 8) * N_SEQ + n] =
                    make_float2((p1.x + c[2]) * a, (p1.y + c[3]) * a);
            } else {
                float b0 = __ldg(&bias[n]), b1 = __ldg(&bias[n + 1]);
                float x0 = p0.x + c[0] + b0, x1 = p0.y + c[1] + b1;
                float y0 = p1.x + c[2] + b0, y1 = p1.y + c[3] + b1;
                if (MODE == 1) {
                    *(float2*)&g_v[(size_t)m0 * HALF_K + n]       = make_float2(x0, x1);
                    *(float2*)&g_v[(size_t)(m0 + 8) * HALF_K + n] = make_float2(y0, y1);
                }
                __nv_bfloat16* dsth = (MODE == 0) ? g_kh : g_vh;
                __nv_bfloat16* dstl = (MODE == 0) ? g_kl : g_vl;
                uint32_t h, l;
                split2(x0, x1, h, l);
                *(uint32_t*)&dsth[(size_t)m0 * HALF_K + n] = h;
                *(uint32_t*)&dstl[(size_t)m0 * HALF_K + n] = l;
                split2(y0, y1, h, l);
                *(uint32_t*)&dsth[(size_t)(m0 + 8) * HALF_K + n] = h;
                *(uint32_t*)&dstl[(size_t)(m0 + 8) * HALF_K + n] = l;
            }
        }
    }
}

// ---------------- fast exp on the FMA pipe (no MUFU) -------------------------
__device__ __forceinline__ float fast_exp(float x) {
    x = fmaxf(x, -87.0f);
    const float L2E = 1.4426950408889634f;
    float t = x * L2E;
    float z = t + 12582912.0f;
    float n = z - 12582912.0f;
    float f = t - n;
    int   i = __float_as_int(z) - 0x4B400000;
    float p = 1.3333558146e-3f;
    p = fmaf(p, f, 9.6181291076e-3f);
    p = fmaf(p, f, 5.5504108665e-2f);
    p = fmaf(p, f, 2.4022650696e-1f);
    p = fmaf(p, f, 6.9314718056e-1f);
    p = fmaf(p, f, 1.0f);
    float sc = __int_as_float((i + 127) << 23);
    return p * sc;
}

__device__ __forceinline__ void combine(float& m, float& Z, float& c, int& bi,
                                        float m2, float Z2, float c2, int bi2) {
    float M  = fmaxf(m, m2);
    float r1 = fast_exp(m  - M);
    float r2 = fast_exp(m2 - M);
    Z = Z * r1 + Z2 * r2;
    float ca = c  * r1;
    float cb = c2 * r2;
    if (cb > ca || (cb == ca && bi2 < bi)) { c = cb; bi = bi2; }
    else                                   { c = ca; }
    m = M;
}

__global__ __launch_bounds__(256)
void softmax_combine_kernel(float* __restrict__ out)
{
    const int row = blockIdx.x;
    const float4* __restrict__ S4 = (const float4*)(g_s + (size_t)row * N_SEQ);
    const float4* __restrict__ V4 = (const float4*)(g_v + (size_t)row * N_SEQ);
    const int tid = threadIdx.x;

    float m = -INFINITY, Z = 0.0f, c = -INFINITY;
    int bi = 0;

    #pragma unroll
    for (int it = 0; it < 4; it++) {
        int q = tid + it * 256;
        float4 s4 = S4[q];
        float4 v4 = V4[q];
        float ss[4] = {s4.x, s4.y, s4.z, s4.w};
        float vv[4] = {v4.x, v4.y, v4.z, v4.w};
        #pragma unroll
        for (int l = 0; l < 4; l++) {
            float s = ss[l];
            int   j = q * 4 + l;
            if (s > m) {
                float r = fast_exp(m - s);
                Z = Z * r + 1.0f;
                c = c * r;
                float cand = vv[l];
                if (cand > c || (cand == c && j < bi)) { c = cand; bi = j; }
                m = s;
            } else {
                float e = fast_exp(s - m);
                Z += e;
                float cand = e * vv[l];
                if (cand > c || (cand == c && j < bi)) { c = cand; bi = j; }
            }
        }
    }

    const unsigned full = 0xffffffffu;
    #pragma unroll
    for (int off = 16; off > 0; off >>= 1) {
        float m2 = __shfl_down_sync(full, m, off);
        float Z2 = __shfl_down_sync(full, Z, off);
        float c2 = __shfl_down_sync(full, c, off);
        int   b2 = __shfl_down_sync(full, bi, off);
        combine(m, Z, c, bi, m2, Z2, c2, b2);
    }

    __shared__ float sm[8], sz[8], sc[8];
    __shared__ int   sbuf[8];
    int wid = tid >> 5, lane = tid & 31;
    if (lane == 0) { sm[wid] = m; sz[wid] = Z; sc[wid] = c; sbuf[wid] = bi; }
    __syncthreads();
    if (tid == 0) {
        #pragma unroll
        for (int w = 1; w < 8; w++)
            combine(m, Z, c, bi, sm[w], sz[w], sc[w], sbuf[w]);
        out[row]         = c / Z;
        out[N_SEQ + row] = (float)bi;
    }
}

// ---------------- launch ------------------------------------------------------
extern "C" void kernel_launch(void* const* d_in, const int* in_sizes, int n_in,
                              void* d_out, int out_size)
{
    const float* x  = (const float*)d_in[0];
    const float* Wk = (const float*)d_in[1];
    const float* bk = (const float*)d_in[2];
    const float* Wv = (const float*)d_in[3];
    const float* bv = (const float*)d_in[4];
    // d_in[5]/d_in[6] (Wq,bq) are dead in the reference (x_q = x@Wv+bv)
    float* out = (float*)d_out;

    static bool attr_done = false;
    if (!attr_done) {
        cudaFuncSetAttribute(gemm_p1_kernel<0>, cudaFuncAttributeMaxDynamicSharedMemorySize, P1_SMEM);
        cudaFuncSetAttribute(gemm_p1_kernel<1>, cudaFuncAttributeMaxDynamicSharedMemorySize, P1_SMEM);
        cudaFuncSetAttribute(gemm_p1_kernel<2>, cudaFuncAttributeMaxDynamicSharedMemorySize, P1_SMEM);
        cudaFuncSetAttribute(gemm_p2_kernel<0>, cudaFuncAttributeMaxDynamicSharedMemorySize, P2_SMEM);
        cudaFuncSetAttribute(gemm_p2_kernel<1>, cudaFuncAttributeMaxDynamicSharedMemorySize, P2_SMEM);
        cudaFuncSetAttribute(gemm_p2_kernel<2>, cudaFuncAttributeMaxDynamicSharedMemorySize, P2_SMEM);
        attr_done = true;
    }

    // 1) split x into bf16 hi/lo
    convert_x_kernel<<<8192, 256>>>(x);
    // 2) transpose+split weights
    dim3 tg(HALF_K / 32, SIZE_K / 32);
    transpose_split_kernel<0><<<tg, dim3(32, 8)>>>(Wk);
    transpose_split_kernel<1><<<tg, dim3(32, 8)>>>(Wv);
    // 3) projections: pass1 (hh+lh) then pass2 (hl + epilogue)
    dim3 g1(N_SEQ / 128, HALF_K / 128);   // 32 x 32
    dim3 g2(N_SEQ / 128, HALF_K / 256);   // 32 x 16
    gemm_p1_kernel<0><<<g1, GT, P1_SMEM>>>();
    gemm_p2_kernel<0><<<g2, GT, P2_SMEM>>>(bk);
    gemm_p1_kernel<1><<<g1, GT, P1_SMEM>>>();
    gemm_p2_kernel<1><<<g2, GT, P2_SMEM>>>(bv);
    // 4) scores: pass1 (hh+lh) then pass2 (hl + scale)
    dim3 s1(N_SEQ / 128, N_SEQ / 128);    // 32 x 32
    dim3 s2(N_SEQ / 128, N_SEQ / 256);    // 32 x 16
    gemm_p1_kernel<2><<<s1, GT, P1_SMEM>>>();
    gemm_p2_kernel<2><<<s2, GT, P2_SMEM>>>(nullptr);
    // 5) softmax + elementwise V + row max/argmax
    softmax_combine_kernel<<<N_SEQ, 256>>>(out);
}

// round 16
// speedup vs baseline: 1.3808x; 1.3081x over previous
#include <cuda_runtime.h>
#include <cuda_bf16.h>
#include <math.h>
#include <stdint.h>

#define N_SEQ  4096
#define SIZE_K 8192
#define HALF_K 4096

// ---------------- scratch (static device globals; no runtime alloc) ----------
__device__ __nv_bfloat16 g_xh[(size_t)N_SEQ * SIZE_K];
__device__ __nv_bfloat16 g_xl[(size_t)N_SEQ * SIZE_K];
__device__ __nv_bfloat16 g_wkh[(size_t)HALF_K * SIZE_K];   // Wk^T hi  [4096,8192]
__device__ __nv_bfloat16 g_wkl[(size_t)HALF_K * SIZE_K];
__device__ __nv_bfloat16 g_wvh[(size_t)HALF_K * SIZE_K];
__device__ __nv_bfloat16 g_wvl[(size_t)HALF_K * SIZE_K];
__device__ __nv_bfloat16 g_kh[(size_t)N_SEQ * HALF_K];     // K split
__device__ __nv_bfloat16 g_kl[(size_t)N_SEQ * HALF_K];
__device__ __nv_bfloat16 g_vh[(size_t)N_SEQ * HALF_K];     // V split
__device__ __nv_bfloat16 g_vl[(size_t)N_SEQ * HALF_K];
__device__ float         g_v [(size_t)N_SEQ * HALF_K];     // V fp32
__device__ float         g_s [(size_t)N_SEQ * N_SEQ];      // scores fp32

// ---------------- PTX helpers (base sm_103 features only) --------------------
static __device__ __forceinline__ uint32_t smem_u32(const void* p) {
    uint32_t a;
    asm("{ .reg .u64 t; cvta.to.shared.u64 t, %1; cvt.u32.u64 %0, t; }" : "=r"(a) : "l"(p));
    return a;
}
static __device__ __forceinline__ void cp16(uint32_t s, const void* g) {
    asm volatile("cp.async.cg.shared.global [%0], [%1], 16;" :: "r"(s), "l"(g));
}
static __device__ __forceinline__ void cp_commit() {
    asm volatile("cp.async.commit_group;" ::: "memory");
}
template<int NP> static __device__ __forceinline__ void cp_wait() {
    asm volatile("cp.async.wait_group %0;" :: "n"(NP) : "memory");
}
static __device__ __forceinline__ void ldsm4(uint32_t* r, uint32_t addr) {
    asm volatile("ldmatrix.sync.aligned.m8n8.x4.shared.b16 {%0,%1,%2,%3}, [%4];"
        : "=r"(r[0]), "=r"(r[1]), "=r"(r[2]), "=r"(r[3]) : "r"(addr));
}
static __device__ __forceinline__ void mma16816(float* c, const uint32_t* a, const uint32_t* b) {
    asm volatile(
        "mma.sync.aligned.m16n8k16.row.col.f32.bf16.bf16.f32 "
        "{%0,%1,%2,%3}, {%4,%5,%6,%7}, {%8,%9}, {%0,%1,%2,%3};"
        : "+f"(c[0]), "+f"(c[1]), "+f"(c[2]), "+f"(c[3])
        : "r"(a[0]), "r"(a[1]), "r"(a[2]), "r"(a[3]), "r"(b[0]), "r"(b[1]));
}
static __device__ __forceinline__ void split2(float x0, float x1, uint32_t& h, uint32_t& l) {
    __nv_bfloat16 h0 = __float2bfloat16(x0), h1 = __float2bfloat16(x1);
    __nv_bfloat16 l0 = __float2bfloat16(x0 - __bfloat162float(h0));
    __nv_bfloat16 l1 = __float2bfloat16(x1 - __bfloat162float(h1));
    h = (uint32_t)__bfloat16_as_ushort(h0) | ((uint32_t)__bfloat16_as_ushort(h1) << 16);
    l = (uint32_t)__bfloat16_as_ushort(l0) | ((uint32_t)__bfloat16_as_ushort(l1) << 16);
}

// ---------------- convert / split kernels ------------------------------------
__global__ __launch_bounds__(256)
void convert_x_kernel(const float* __restrict__ x)
{
    const size_t total4 = (size_t)N_SEQ * SIZE_K / 4;
    __nv_bfloat162* xh2 = reinterpret_cast<__nv_bfloat162*>(g_xh);
    __nv_bfloat162* xl2 = reinterpret_cast<__nv_bfloat162*>(g_xl);
    for (size_t i = (size_t)blockIdx.x * blockDim.x + threadIdx.x; i < total4;
         i += (size_t)gridDim.x * blockDim.x) {
        float4 v = reinterpret_cast<const float4*>(x)[i];
        __nv_bfloat16 h0 = __float2bfloat16(v.x), h1 = __float2bfloat16(v.y);
        __nv_bfloat16 h2 = __float2bfloat16(v.z), h3 = __float2bfloat16(v.w);
        __nv_bfloat16 l0 = __float2bfloat16(v.x - __bfloat162float(h0));
        __nv_bfloat16 l1 = __float2bfloat16(v.y - __bfloat162float(h1));
        __nv_bfloat16 l2 = __float2bfloat16(v.z - __bfloat162float(h2));
        __nv_bfloat16 l3 = __float2bfloat16(v.w - __bfloat162float(h3));
        xh2[2 * i]     = __nv_bfloat162(h0, h1);
        xh2[2 * i + 1] = __nv_bfloat162(h2, h3);
        xl2[2 * i]     = __nv_bfloat162(l0, l1);
        xl2[2 * i + 1] = __nv_bfloat162(l2, l3);
    }
}

// W [SIZE_K, HALF_K] fp32 -> WT hi/lo [HALF_K, SIZE_K] bf16 (both W in one launch)
__global__ __launch_bounds__(256)
void transpose_split_kernel(const float* __restrict__ Wk, const float* __restrict__ Wv)
{
    const float* W = (blockIdx.z == 0) ? Wk : Wv;
    __nv_bfloat16* dh = (blockIdx.z == 0) ? g_wkh : g_wvh;
    __nv_bfloat16* dl = (blockIdx.z == 0) ? g_wkl : g_wvl;
    __shared__ float t[32][33];
    int n0 = blockIdx.x * 32;
    int k0 = blockIdx.y * 32;
    int tx = threadIdx.x, ty = threadIdx.y;   // block (32, 8)
    #pragma unroll
    for (int i = 0; i < 4; i++)
        t[ty + i * 8][tx] = W[(size_t)(k0 + ty + i * 8) * HALF_K + n0 + tx];
    __syncthreads();
    #pragma unroll
    for (int i = 0; i < 4; i++) {
        int n = n0 + ty + i * 8;
        int k = k0 + tx;
        float v = t[tx][ty + i * 8];
        __nv_bfloat16 h = __float2bfloat16(v);
        __nv_bfloat16 l = __float2bfloat16(v - __bfloat162float(h));
        dh[(size_t)n * SIZE_K + k] = h;
        dl[(size_t)n * SIZE_K + k] = l;
    }
}

// ---------------- bf16 3-term GEMM: 4 warps, 64x64 warp tile -----------------
// PROJ=1: z=0 -> K proj (bias bk), z=1 -> V proj (bias bv), K=8192
// PROJ=0: scores S = (V K^T)/90, K=4096
// CTA 128x128, 128 threads (2x2 warps of 64x64). BKC=32.
// stage 32 KB: Ah 8K | Al 8K | Bh 8K | Bl 8K. 3 stages = 96 KB, occ 2.
#define G_STG 32768u
#define G_BUF 8192u
#define G_NSTG 3
#define G_SMEM (G_NSTG * G_STG)

template<int PROJ>
__global__ __launch_bounds__(128, 2)
void gemm3_kernel(const float* __restrict__ bk, const float* __restrict__ bv)
{
    const __nv_bfloat16 *Ah, *Al, *Bh, *Bl;
    int Ktot;
    if (PROJ) {
        Ah = g_xh; Al = g_xl; Ktot = SIZE_K;
        if (blockIdx.z == 0) { Bh = g_wkh; Bl = g_wkl; }
        else                 { Bh = g_wvh; Bl = g_wvl; }
    } else {
        Ah = g_vh; Al = g_vl; Bh = g_kh; Bl = g_kl; Ktot = HALF_K;
    }

    extern __shared__ char smem[];
    const uint32_t sb = smem_u32(smem);
    const int tid  = threadIdx.x;
    const int wid  = tid >> 5;
    const int lane = tid & 31;
    const int wm   = wid & 1;     // warp row 0..1 (64 rows each)
    const int wn   = wid >> 1;    // warp col 0..1 (64 cols each)

    const int bm = blockIdx.x * 128;
    const int bn = blockIdx.y * 128;

    float acc[4][8][4];   // [mt 16-row tile][n8][frag]
    #pragma unroll
    for (int mt = 0; mt < 4; mt++)
        #pragma unroll
        for (int n = 0; n < 8; n++)
            #pragma unroll
            for (int q = 0; q < 4; q++) acc[mt][n][q] = 0.0f;

    const int nch = Ktot / 32;

    auto load_chunk = [&](int ch) {
        const uint32_t stg = sb + (uint32_t)(ch % G_NSTG) * G_STG;
        const size_t k0 = (size_t)ch * 32;
        #pragma unroll
        for (int i = 0; i < 4; i++) {
            int pos = tid + i * 128;           // 0..511
            int row = pos >> 2, seg = pos & 3;
            uint32_t soff = row * 64 + ((seg ^ ((row >> 1) & 3)) << 4);
            size_t ga = (size_t)(bm + row) * Ktot + k0 + seg * 8;
            size_t gb = (size_t)(bn + row) * Ktot + k0 + seg * 8;
            cp16(stg +            soff, Ah + ga);
            cp16(stg +   G_BUF + soff, Al + ga);
            cp16(stg + 2*G_BUF + soff, Bh + gb);
            cp16(stg + 3*G_BUF + soff, Bl + gb);
        }
    };

    load_chunk(0); cp_commit();
    load_chunk(1); cp_commit();

    for (int ch = 0; ch < nch; ++ch) {
        cp_wait<1>();
        __syncthreads();
        if (ch + 2 < nch) load_chunk(ch + 2);
        cp_commit();

        const uint32_t stg = sb + (uint32_t)(ch % G_NSTG) * G_STG;

        #pragma unroll
        for (int k16 = 0; k16 < 2; ++k16) {
            uint32_t afh[4][4], afl[4][4];
            #pragma unroll
            for (int mt = 0; mt < 4; ++mt) {
                int row = wm * 64 + mt * 16 + (lane & 15);
                int seg = k16 * 2 + (lane >> 4);
                uint32_t off = row * 64 + ((seg ^ ((row >> 1) & 3)) << 4);
                ldsm4(afh[mt], stg + off);
                ldsm4(afl[mt], stg + G_BUF + off);
            }
            #pragma unroll
            for (int p = 0; p < 4; ++p) {
                int row = wn * 64 + p * 16 + ((lane >> 4) << 3) + (lane & 7);
                int seg = k16 * 2 + ((lane >> 3) & 1);
                uint32_t off = row * 64 + ((seg ^ ((row >> 1) & 3)) << 4);
                uint32_t bh[4], bl[4];
                ldsm4(bh, stg + 2*G_BUF + off);
                ldsm4(bl, stg + 3*G_BUF + off);
                // hh
                #pragma unroll
                for (int mt = 0; mt < 4; ++mt) {
                    mma16816(acc[mt][2 * p],     afh[mt], &bh[0]);
                    mma16816(acc[mt][2 * p + 1], afh[mt], &bh[2]);
                }
                // hl
                #pragma unroll
                for (int mt = 0; mt < 4; ++mt) {
                    mma16816(acc[mt][2 * p],     afh[mt], &bl[0]);
                    mma16816(acc[mt][2 * p + 1], afh[mt], &bl[2]);
                }
                // lh
                #pragma unroll
                for (int mt = 0; mt < 4; ++mt) {
                    mma16816(acc[mt][2 * p],     afl[mt], &bh[0]);
                    mma16816(acc[mt][2 * p + 1], afl[mt], &bh[2]);
                }
            }
        }
    }

    // ---- epilogue: frag c0,c1 @ (row, col..col+1), c2,c3 @ (row+8)
    const float* bias = (PROJ && blockIdx.z == 1) ? bv : bk;
    #pragma unroll
    for (int mt = 0; mt < 4; ++mt) {
        #pragma unroll
        for (int nt = 0; nt < 8; ++nt) {
            float* c = acc[mt][nt];
            const int n  = bn + wn * 64 + nt * 8 + (lane & 3) * 2;
            const int m0 = bm + wm * 64 + mt * 16 + (lane >> 2);
            if (!PROJ) {
                const float a = 1.0f / 90.0f;
                *(float2*)&g_s[(size_t)m0 * N_SEQ + n]       = make_float2(c[0] * a, c[1] * a);
                *(float2*)&g_s[(size_t)(m0 + 8) * N_SEQ + n] = make_float2(c[2] * a, c[3] * a);
            } else {
                float b0 = __ldg(&bias[n]), b1 = __ldg(&bias[n + 1]);
                float x0 = c[0] + b0, x1 = c[1] + b1;
                float y0 = c[2] + b0, y1 = c[3] + b1;
                if (blockIdx.z == 1) {
                    *(float2*)&g_v[(size_t)m0 * HALF_K + n]       = make_float2(x0, x1);
                    *(float2*)&g_v[(size_t)(m0 + 8) * HALF_K + n] = make_float2(y0, y1);
                }
                __nv_bfloat16* dsth = (blockIdx.z == 0) ? g_kh : g_vh;
                __nv_bfloat16* dstl = (blockIdx.z == 0) ? g_kl : g_vl;
                uint32_t h, l;
                split2(x0, x1, h, l);
                *(uint32_t*)&dsth[(size_t)m0 * HALF_K + n] = h;
                *(uint32_t*)&dstl[(size_t)m0 * HALF_K + n] = l;
                split2(y0, y1, h, l);
                *(uint32_t*)&dsth[(size_t)(m0 + 8) * HALF_K + n] = h;
                *(uint32_t*)&dstl[(size_t)(m0 + 8) * HALF_K + n] = l;
            }
        }
    }
}

// ---------------- fast exp on the FMA pipe (no MUFU) -------------------------
__device__ __forceinline__ float fast_exp(float x) {
    x = fmaxf(x, -87.0f);
    const float L2E = 1.4426950408889634f;
    float t = x * L2E;
    float z = t + 12582912.0f;
    float n = z - 12582912.0f;
    float f = t - n;
    int   i = __float_as_int(z) - 0x4B400000;
    float p = 1.3333558146e-3f;
    p = fmaf(p, f, 9.6181291076e-3f);
    p = fmaf(p, f, 5.5504108665e-2f);
    p = fmaf(p, f, 2.4022650696e-1f);
    p = fmaf(p, f, 6.9314718056e-1f);
    p = fmaf(p, f, 1.0f);
    float sc = __int_as_float((i + 127) << 23);
    return p * sc;
}

__device__ __forceinline__ void combine(float& m, float& Z, float& c, int& bi,
                                        float m2, float Z2, float c2, int bi2) {
    float M  = fmaxf(m, m2);
    float r1 = fast_exp(m  - M);
    float r2 = fast_exp(m2 - M);
    Z = Z * r1 + Z2 * r2;
    float ca = c  * r1;
    float cb = c2 * r2;
    if (cb > ca || (cb == ca && bi2 < bi)) { c = cb; bi = bi2; }
    else                                   { c = ca; }
    m = M;
}

__global__ __launch_bounds__(256)
void softmax_combine_kernel(float* __restrict__ out)
{
    const int row = blockIdx.x;
    const float4* __restrict__ S4 = (const float4*)(g_s + (size_t)row * N_SEQ);
    const float4* __restrict__ V4 = (const float4*)(g_v + (size_t)row * N_SEQ);
    const int tid = threadIdx.x;

    float m = -INFINITY, Z = 0.0f, c = -INFINITY;
    int bi = 0;

    #pragma unroll
    for (int it = 0; it < 4; it++) {
        int q = tid + it * 256;
        float4 s4 = S4[q];
        float4 v4 = V4[q];
        float ss[4] = {s4.x, s4.y, s4.z, s4.w};
        float vv[4] = {v4.x, v4.y, v4.z, v4.w};
        #pragma unroll
        for (int l = 0; l < 4; l++) {
            float s = ss[l];
            int   j = q * 4 + l;
            if (s > m) {
                float r = fast_exp(m - s);
                Z = Z * r + 1.0f;
                c = c * r;
                float cand = vv[l];
                if (cand > c || (cand == c && j < bi)) { c = cand; bi = j; }
                m = s;
            } else {
                float e = fast_exp(s - m);
                Z += e;
                float cand = e * vv[l];
                if (cand > c || (cand == c && j < bi)) { c = cand; bi = j; }
            }
        }
    }

    const unsigned full = 0xffffffffu;
    #pragma unroll
    for (int off = 16; off > 0; off >>= 1) {
        float m2 = __shfl_down_sync(full, m, off);
        float Z2 = __shfl_down_sync(full, Z, off);
        float c2 = __shfl_down_sync(full, c, off);
        int   b2 = __shfl_down_sync(full, bi, off);
        combine(m, Z, c, bi, m2, Z2, c2, b2);
    }

    __shared__ float sm[8], sz[8], sc[8];
    __shared__ int   sbuf[8];
    int wid = tid >> 5, lane = tid & 31;
    if (lane == 0) { sm[wid] = m; sz[wid] = Z; sc[wid] = c; sbuf[wid] = bi; }
    __syncthreads();
    if (tid == 0) {
        #pragma unroll
        for (int w = 1; w < 8; w++)
            combine(m, Z, c, bi, sm[w], sz[w], sc[w], sbuf[w]);
        out[row]         = c / Z;
        out[N_SEQ + row] = (float)bi;
    }
}

// ---------------- launch ------------------------------------------------------
extern "C" void kernel_launch(void* const* d_in, const int* in_sizes, int n_in,
                              void* d_out, int out_size)
{
    const float* x  = (const float*)d_in[0];
    const float* Wk = (const float*)d_in[1];
    const float* bk = (const float*)d_in[2];
    const float* Wv = (const float*)d_in[3];
    const float* bv = (const float*)d_in[4];
    // d_in[5]/d_in[6] (Wq,bq) are dead in the reference (x_q = x@Wv+bv)
    float* out = (float*)d_out;

    static bool attr_done = false;
    if (!attr_done) {
        cudaFuncSetAttribute(gemm3_kernel<1>, cudaFuncAttributeMaxDynamicSharedMemorySize, G_SMEM);
        cudaFuncSetAttribute(gemm3_kernel<0>, cudaFuncAttributeMaxDynamicSharedMemorySize, G_SMEM);
        attr_done = true;
    }

    // 1) split x into bf16 hi/lo
    convert_x_kernel<<<8192, 256>>>(x);
    // 2) transpose+split both weights in one launch
    dim3 tg(HALF_K / 32, SIZE_K / 32, 2);
    transpose_split_kernel<<<tg, dim3(32, 8)>>>(Wk, Wv);
    // 3) both projections in ONE launch (z: 0=K, 1=V) — 2048 CTAs, ~1% tail
    dim3 gproj(N_SEQ / 128, HALF_K / 128, 2);
    gemm3_kernel<1><<<gproj, 128, G_SMEM>>>(bk, bv);
    // 4) scores
    dim3 gsc(N_SEQ / 128, N_SEQ / 128, 1);
    gemm3_kernel<0><<<gsc, 128, G_SMEM>>>(nullptr, nullptr);
    // 5) softmax + elementwise V + row max/argmax
    softmax_combine_kernel<<<N_SEQ, 256>>>(out);
}

// round 17
// speedup vs baseline: 1.4051x; 1.0176x over previous
#include <cuda_runtime.h>
#include <cuda_bf16.h>
#include <math.h>
#include <stdint.h>

#define N_SEQ  4096
#define SIZE_K 8192
#define HALF_K 4096

// ---------------- scratch (static device globals; no runtime alloc) ----------
__device__ __nv_bfloat16 g_xh[(size_t)N_SEQ * SIZE_K];
__device__ __nv_bfloat16 g_xl[(size_t)N_SEQ * SIZE_K];
__device__ __nv_bfloat16 g_wkh[(size_t)HALF_K * SIZE_K];   // Wk^T hi  [4096,8192]
__device__ __nv_bfloat16 g_wkl[(size_t)HALF_K * SIZE_K];
__device__ __nv_bfloat16 g_wvh[(size_t)HALF_K * SIZE_K];
__device__ __nv_bfloat16 g_wvl[(size_t)HALF_K * SIZE_K];
__device__ __nv_bfloat16 g_kh[(size_t)N_SEQ * HALF_K];     // K split
__device__ __nv_bfloat16 g_kl[(size_t)N_SEQ * HALF_K];
__device__ __nv_bfloat16 g_vh[(size_t)N_SEQ * HALF_K];     // V split
__device__ __nv_bfloat16 g_vl[(size_t)N_SEQ * HALF_K];
__device__ float         g_v [(size_t)N_SEQ * HALF_K];     // V fp32
__device__ float         g_s [(size_t)N_SEQ * N_SEQ];      // scores fp32

// ---------------- PTX helpers (base sm_103 features only) --------------------
static __device__ __forceinline__ uint32_t smem_u32(const void* p) {
    uint32_t a;
    asm("{ .reg .u64 t; cvta.to.shared.u64 t, %1; cvt.u32.u64 %0, t; }" : "=r"(a) : "l"(p));
    return a;
}
static __device__ __forceinline__ void cp16(uint32_t s, const void* g) {
    asm volatile("cp.async.cg.shared.global [%0], [%1], 16;" :: "r"(s), "l"(g));
}
static __device__ __forceinline__ void cp_commit() {
    asm volatile("cp.async.commit_group;" ::: "memory");
}
template<int NP> static __device__ __forceinline__ void cp_wait() {
    asm volatile("cp.async.wait_group %0;" :: "n"(NP) : "memory");
}
static __device__ __forceinline__ void ldsm4(uint32_t* r, uint32_t addr) {
    asm volatile("ldmatrix.sync.aligned.m8n8.x4.shared.b16 {%0,%1,%2,%3}, [%4];"
        : "=r"(r[0]), "=r"(r[1]), "=r"(r[2]), "=r"(r[3]) : "r"(addr));
}
static __device__ __forceinline__ void mma16816(float* c, const uint32_t* a, const uint32_t* b) {
    asm volatile(
        "mma.sync.aligned.m16n8k16.row.col.f32.bf16.bf16.f32 "
        "{%0,%1,%2,%3}, {%4,%5,%6,%7}, {%8,%9}, {%0,%1,%2,%3};"
        : "+f"(c[0]), "+f"(c[1]), "+f"(c[2]), "+f"(c[3])
        : "r"(a[0]), "r"(a[1]), "r"(a[2]), "r"(a[3]), "r"(b[0]), "r"(b[1]));
}
static __device__ __forceinline__ void split2(float x0, float x1, uint32_t& h, uint32_t& l) {
    __nv_bfloat16 h0 = __float2bfloat16(x0), h1 = __float2bfloat16(x1);
    __nv_bfloat16 l0 = __float2bfloat16(x0 - __bfloat162float(h0));
    __nv_bfloat16 l1 = __float2bfloat16(x1 - __bfloat162float(h1));
    h = (uint32_t)__bfloat16_as_ushort(h0) | ((uint32_t)__bfloat16_as_ushort(h1) << 16);
    l = (uint32_t)__bfloat16_as_ushort(l0) | ((uint32_t)__bfloat16_as_ushort(l1) << 16);
}

// ---------------- convert / split kernels ------------------------------------
__global__ __launch_bounds__(256)
void convert_x_kernel(const float* __restrict__ x)
{
    const size_t total4 = (size_t)N_SEQ * SIZE_K / 4;
    __nv_bfloat162* xh2 = reinterpret_cast<__nv_bfloat162*>(g_xh);
    __nv_bfloat162* xl2 = reinterpret_cast<__nv_bfloat162*>(g_xl);
    for (size_t i = (size_t)blockIdx.x * blockDim.x + threadIdx.x; i < total4;
         i += (size_t)gridDim.x * blockDim.x) {
        float4 v = reinterpret_cast<const float4*>(x)[i];
        __nv_bfloat16 h0 = __float2bfloat16(v.x), h1 = __float2bfloat16(v.y);
        __nv_bfloat16 h2 = __float2bfloat16(v.z), h3 = __float2bfloat16(v.w);
        __nv_bfloat16 l0 = __float2bfloat16(v.x - __bfloat162float(h0));
        __nv_bfloat16 l1 = __float2bfloat16(v.y - __bfloat162float(h1));
        __nv_bfloat16 l2 = __float2bfloat16(v.z - __bfloat162float(h2));
        __nv_bfloat16 l3 = __float2bfloat16(v.w - __bfloat162float(h3));
        xh2[2 * i]     = __nv_bfloat162(h0, h1);
        xh2[2 * i + 1] = __nv_bfloat162(h2, h3);
        xl2[2 * i]     = __nv_bfloat162(l0, l1);
        xl2[2 * i + 1] = __nv_bfloat162(l2, l3);
    }
}

// W [SIZE_K, HALF_K] fp32 -> WT hi/lo [HALF_K, SIZE_K] bf16 (both W in one launch)
__global__ __launch_bounds__(256)
void transpose_split_kernel(const float* __restrict__ Wk, const float* __restrict__ Wv)
{
    const float* W = (blockIdx.z == 0) ? Wk : Wv;
    __nv_bfloat16* dh = (blockIdx.z == 0) ? g_wkh : g_wvh;
    __nv_bfloat16* dl = (blockIdx.z == 0) ? g_wkl : g_wvl;
    __shared__ float t[32][33];
    int n0 = blockIdx.x * 32;
    int k0 = blockIdx.y * 32;
    int tx = threadIdx.x, ty = threadIdx.y;   // block (32, 8)
    #pragma unroll
    for (int i = 0; i < 4; i++)
        t[ty + i * 8][tx] = W[(size_t)(k0 + ty + i * 8) * HALF_K + n0 + tx];
    __syncthreads();
    #pragma unroll
    for (int i = 0; i < 4; i++) {
        int n = n0 + ty + i * 8;
        int k = k0 + tx;
        float v = t[tx][ty + i * 8];
        __nv_bfloat16 h = __float2bfloat16(v);
        __nv_bfloat16 l = __float2bfloat16(v - __bfloat162float(h));
        dh[(size_t)n * SIZE_K + k] = h;
        dl[(size_t)n * SIZE_K + k] = l;
    }
}

// ======== PROJ GEMM: CTA 128x256, 8 warps (2x4) of 64x64, BKC=64, 2 stages ===
// z=0 -> K proj (bias bk), z=1 -> V proj (bias bv). K=8192.
// stage 96 KB: Ah 16K | Al 16K | Bh 32K | Bl 32K. Rows 128B, swizzle seg^(row&7).
#define PR_STG  98304u
#define PR_OAL  16384u
#define PR_OBH  32768u
#define PR_OBL  65536u
#define PR_SMEM (2 * PR_STG)

__global__ __launch_bounds__(256, 1)
void gemm_proj_kernel(const float* __restrict__ bk, const float* __restrict__ bv)
{
    const __nv_bfloat16* Ah = g_xh;
    const __nv_bfloat16* Al = g_xl;
    const __nv_bfloat16* Bh = (blockIdx.z == 0) ? g_wkh : g_wvh;
    const __nv_bfloat16* Bl = (blockIdx.z == 0) ? g_wkl : g_wvl;
    const int Ktot = SIZE_K;

    extern __shared__ char smem[];
    const uint32_t sb = smem_u32(smem);
    const int tid  = threadIdx.x;
    const int wid  = tid >> 5;
    const int lane = tid & 31;
    const int wm   = wid & 1;     // warp row 0..1 (64 rows each)
    const int wn   = wid >> 1;    // warp col 0..3 (64 cols each)

    const int bm = blockIdx.x * 128;
    const int bn = blockIdx.y * 256;

    float acc[4][8][4];
    #pragma unroll
    for (int mt = 0; mt < 4; mt++)
        #pragma unroll
        for (int n = 0; n < 8; n++)
            #pragma unroll
            for (int q = 0; q < 4; q++) acc[mt][n][q] = 0.0f;

    const int nch = Ktot / 64;

    auto load_chunk = [&](int ch) {
        const uint32_t stg = sb + (uint32_t)(ch & 1) * PR_STG;
        const size_t k0 = (size_t)ch * 64;
        // A: 128 rows x 128B, hi+lo
        #pragma unroll
        for (int i = 0; i < 4; i++) {
            int pos = tid + i * 256;           // 0..1023
            int row = pos >> 3, seg = pos & 7;
            uint32_t soff = row * 128 + ((seg ^ (row & 7)) << 4);
            size_t ga = (size_t)(bm + row) * Ktot + k0 + seg * 8;
            cp16(stg +           soff, Ah + ga);
            cp16(stg + PR_OAL + soff, Al + ga);
        }
        // B: 256 rows x 128B, hi+lo
        #pragma unroll
        for (int i = 0; i < 8; i++) {
            int pos = tid + i * 256;           // 0..2047
            int row = pos >> 3, seg = pos & 7;
            uint32_t soff = row * 128 + ((seg ^ (row & 7)) << 4);
            size_t gb = (size_t)(bn + row) * Ktot + k0 + seg * 8;
            cp16(stg + PR_OBH + soff, Bh + gb);
            cp16(stg + PR_OBL + soff, Bl + gb);
        }
    };

    load_chunk(0); cp_commit();

    for (int ch = 0; ch < nch; ++ch) {
        if (ch + 1 < nch) { load_chunk(ch + 1); cp_commit(); cp_wait<1>(); }
        else              { cp_wait<0>(); }
        __syncthreads();

        const uint32_t stg = sb + (uint32_t)(ch & 1) * PR_STG;

        #pragma unroll
        for (int k16 = 0; k16 < 4; ++k16) {
            uint32_t afh[4][4], afl[4][4];
            #pragma unroll
            for (int mt = 0; mt < 4; ++mt) {
                int row = wm * 64 + mt * 16 + (lane & 15);
                int seg = k16 * 2 + (lane >> 4);
                uint32_t off = row * 128 + ((seg ^ (row & 7)) << 4);
                ldsm4(afh[mt], stg + off);
                ldsm4(afl[mt], stg + PR_OAL + off);
            }
            #pragma unroll
            for (int p = 0; p < 4; ++p) {
                int row = wn * 64 + p * 16 + ((lane >> 4) << 3) + (lane & 7);
                int seg = k16 * 2 + ((lane >> 3) & 1);
                uint32_t off = row * 128 + ((seg ^ (row & 7)) << 4);
                uint32_t bh[4], bl[4];
                ldsm4(bh, stg + PR_OBH + off);
                ldsm4(bl, stg + PR_OBL + off);
                // hh
                #pragma unroll
                for (int mt = 0; mt < 4; ++mt) {
                    mma16816(acc[mt][2 * p],     afh[mt], &bh[0]);
                    mma16816(acc[mt][2 * p + 1], afh[mt], &bh[2]);
                }
                // hl
                #pragma unroll
                for (int mt = 0; mt < 4; ++mt) {
                    mma16816(acc[mt][2 * p],     afh[mt], &bl[0]);
                    mma16816(acc[mt][2 * p + 1], afh[mt], &bl[2]);
                }
                // lh
                #pragma unroll
                for (int mt = 0; mt < 4; ++mt) {
                    mma16816(acc[mt][2 * p],     afl[mt], &bh[0]);
                    mma16816(acc[mt][2 * p + 1], afl[mt], &bh[2]);
                }
            }
        }
        __syncthreads();
    }

    // ---- epilogue
    const float* bias = (blockIdx.z == 0) ? bk : bv;
    #pragma unroll
    for (int mt = 0; mt < 4; ++mt) {
        #pragma unroll
        for (int nt = 0; nt < 8; ++nt) {
            float* c = acc[mt][nt];
            const int n  = bn + wn * 64 + nt * 8 + (lane & 3) * 2;
            const int m0 = bm + wm * 64 + mt * 16 + (lane >> 2);
            float b0 = __ldg(&bias[n]), b1 = __ldg(&bias[n + 1]);
            float x0 = c[0] + b0, x1 = c[1] + b1;
            float y0 = c[2] + b0, y1 = c[3] + b1;
            if (blockIdx.z == 1) {
                *(float2*)&g_v[(size_t)m0 * HALF_K + n]       = make_float2(x0, x1);
                *(float2*)&g_v[(size_t)(m0 + 8) * HALF_K + n] = make_float2(y0, y1);
            }
            __nv_bfloat16* dsth = (blockIdx.z == 0) ? g_kh : g_vh;
            __nv_bfloat16* dstl = (blockIdx.z == 0) ? g_kl : g_vl;
            uint32_t h, l;
            split2(x0, x1, h, l);
            *(uint32_t*)&dsth[(size_t)m0 * HALF_K + n] = h;
            *(uint32_t*)&dstl[(size_t)m0 * HALF_K + n] = l;
            split2(y0, y1, h, l);
            *(uint32_t*)&dsth[(size_t)(m0 + 8) * HALF_K + n] = h;
            *(uint32_t*)&dstl[(size_t)(m0 + 8) * HALF_K + n] = l;
        }
    }
}

// ======== SCORES GEMM: r16 config (128x128, 4 warps 64x64, BKC=32, occ 2) ====
#define G_STG 32768u
#define G_BUF 8192u
#define G_NSTG 3
#define G_SMEM (G_NSTG * G_STG)

__global__ __launch_bounds__(128, 2)
void gemm_sc_kernel()
{
    const __nv_bfloat16 *Ah = g_vh, *Al = g_vl, *Bh = g_kh, *Bl = g_kl;
    const int Ktot = HALF_K;

    extern __shared__ char smem[];
    const uint32_t sb = smem_u32(smem);
    const int tid  = threadIdx.x;
    const int wid  = tid >> 5;
    const int lane = tid & 31;
    const int wm   = wid & 1;
    const int wn   = wid >> 1;

    const int bm = blockIdx.x * 128;
    const int bn = blockIdx.y * 128;

    float acc[4][8][4];
    #pragma unroll
    for (int mt = 0; mt < 4; mt++)
        #pragma unroll
        for (int n = 0; n < 8; n++)
            #pragma unroll
            for (int q = 0; q < 4; q++) acc[mt][n][q] = 0.0f;

    const int nch = Ktot / 32;

    auto load_chunk = [&](int ch) {
        const uint32_t stg = sb + (uint32_t)(ch % G_NSTG) * G_STG;
        const size_t k0 = (size_t)ch * 32;
        #pragma unroll
        for (int i = 0; i < 4; i++) {
            int pos = tid + i * 128;           // 0..511
            int row = pos >> 2, seg = pos & 3;
            uint32_t soff = row * 64 + ((seg ^ ((row >> 1) & 3)) << 4);
            size_t ga = (size_t)(bm + row) * Ktot + k0 + seg * 8;
            size_t gb = (size_t)(bn + row) * Ktot + k0 + seg * 8;
            cp16(stg +            soff, Ah + ga);
            cp16(stg +   G_BUF + soff, Al + ga);
            cp16(stg + 2*G_BUF + soff, Bh + gb);
            cp16(stg + 3*G_BUF + soff, Bl + gb);
        }
    };

    load_chunk(0); cp_commit();
    load_chunk(1); cp_commit();

    for (int ch = 0; ch < nch; ++ch) {
        cp_wait<1>();
        __syncthreads();
        if (ch + 2 < nch) load_chunk(ch + 2);
        cp_commit();

        const uint32_t stg = sb + (uint32_t)(ch % G_NSTG) * G_STG;

        #pragma unroll
        for (int k16 = 0; k16 < 2; ++k16) {
            uint32_t afh[4][4], afl[4][4];
            #pragma unroll
            for (int mt = 0; mt < 4; ++mt) {
                int row = wm * 64 + mt * 16 + (lane & 15);
                int seg = k16 * 2 + (lane >> 4);
                uint32_t off = row * 64 + ((seg ^ ((row >> 1) & 3)) << 4);
                ldsm4(afh[mt], stg + off);
                ldsm4(afl[mt], stg + G_BUF + off);
            }
            #pragma unroll
            for (int p = 0; p < 4; ++p) {
                int row = wn * 64 + p * 16 + ((lane >> 4) << 3) + (lane & 7);
                int seg = k16 * 2 + ((lane >> 3) & 1);
                uint32_t off = row * 64 + ((seg ^ ((row >> 1) & 3)) << 4);
                uint32_t bh[4], bl[4];
                ldsm4(bh, stg + 2*G_BUF + off);
                ldsm4(bl, stg + 3*G_BUF + off);
                #pragma unroll
                for (int mt = 0; mt < 4; ++mt) {
                    mma16816(acc[mt][2 * p],     afh[mt], &bh[0]);
                    mma16816(acc[mt][2 * p + 1], afh[mt], &bh[2]);
                }
                #pragma unroll
                for (int mt = 0; mt < 4; ++mt) {
                    mma16816(acc[mt][2 * p],     afh[mt], &bl[0]);
                    mma16816(acc[mt][2 * p + 1], afh[mt], &bl[2]);
                }
                #pragma unroll
                for (int mt = 0; mt < 4; ++mt) {
                    mma16816(acc[mt][2 * p],     afl[mt], &bh[0]);
                    mma16816(acc[mt][2 * p + 1], afl[mt], &bh[2]);
                }
            }
        }
    }

    #pragma unroll
    for (int mt = 0; mt < 4; ++mt) {
        #pragma unroll
        for (int nt = 0; nt < 8; ++nt) {
            float* c = acc[mt][nt];
            const int n  = bn + wn * 64 + nt * 8 + (lane & 3) * 2;
            const int m0 = bm + wm * 64 + mt * 16 + (lane >> 2);
            const float a = 1.0f / 90.0f;
            *(float2*)&g_s[(size_t)m0 * N_SEQ + n]       = make_float2(c[0] * a, c[1] * a);
            *(float2*)&g_s[(size_t)(m0 + 8) * N_SEQ + n] = make_float2(c[2] * a, c[3] * a);
        }
    }
}

// ---------------- fast exp on the FMA pipe (no MUFU) -------------------------
__device__ __forceinline__ float fast_exp(float x) {
    x = fmaxf(x, -87.0f);
    const float L2E = 1.4426950408889634f;
    float t = x * L2E;
    float z = t + 12582912.0f;
    float n = z - 12582912.0f;
    float f = t - n;
    int   i = __float_as_int(z) - 0x4B400000;
    float p = 1.3333558146e-3f;
    p = fmaf(p, f, 9.6181291076e-3f);
    p = fmaf(p, f, 5.5504108665e-2f);
    p = fmaf(p, f, 2.4022650696e-1f);
    p = fmaf(p, f, 6.9314718056e-1f);
    p = fmaf(p, f, 1.0f);
    float sc = __int_as_float((i + 127) << 23);
    return p * sc;
}

__device__ __forceinline__ void combine(float& m, float& Z, float& c, int& bi,
                                        float m2, float Z2, float c2, int bi2) {
    float M  = fmaxf(m, m2);
    float r1 = fast_exp(m  - M);
    float r2 = fast_exp(m2 - M);
    Z = Z * r1 + Z2 * r2;
    float ca = c  * r1;
    float cb = c2 * r2;
    if (cb > ca || (cb == ca && bi2 < bi)) { c = cb; bi = bi2; }
    else                                   { c = ca; }
    m = M;
}

__global__ __launch_bounds__(256)
void softmax_combine_kernel(float* __restrict__ out)
{
    const int row = blockIdx.x;
    const float4* __restrict__ S4 = (const float4*)(g_s + (size_t)row * N_SEQ);
    const float4* __restrict__ V4 = (const float4*)(g_v + (size_t)row * N_SEQ);
    const int tid = threadIdx.x;

    float m = -INFINITY, Z = 0.0f, c = -INFINITY;
    int bi = 0;

    #pragma unroll
    for (int it = 0; it < 4; it++) {
        int q = tid + it * 256;
        float4 s4 = S4[q];
        float4 v4 = V4[q];
        float ss[4] = {s4.x, s4.y, s4.z, s4.w};
        float vv[4] = {v4.x, v4.y, v4.z, v4.w};
        #pragma unroll
        for (int l = 0; l < 4; l++) {
            float s = ss[l];
            int   j = q * 4 + l;
            if (s > m) {
                float r = fast_exp(m - s);
                Z = Z * r + 1.0f;
                c = c * r;
                float cand = vv[l];
                if (cand > c || (cand == c && j < bi)) { c = cand; bi = j; }
                m = s;
            } else {
                float e = fast_exp(s - m);
                Z += e;
                float cand = e * vv[l];
                if (cand > c || (cand == c && j < bi)) { c = cand; bi = j; }
            }
        }
    }

    const unsigned full = 0xffffffffu;
    #pragma unroll
    for (int off = 16; off > 0; off >>= 1) {
        float m2 = __shfl_down_sync(full, m, off);
        float Z2 = __shfl_down_sync(full, Z, off);
        float c2 = __shfl_down_sync(full, c, off);
        int   b2 = __shfl_down_sync(full, bi, off);
        combine(m, Z, c, bi, m2, Z2, c2, b2);
    }

    __shared__ float sm[8], sz[8], sc[8];
    __shared__ int   sbuf[8];
    int wid = tid >> 5, lane = tid & 31;
    if (lane == 0) { sm[wid] = m; sz[wid] = Z; sc[wid] = c; sbuf[wid] = bi; }
    __syncthreads();
    if (tid == 0) {
        #pragma unroll
        for (int w = 1; w < 8; w++)
            combine(m, Z, c, bi, sm[w], sz[w], sc[w], sbuf[w]);
        out[row]         = c / Z;
        out[N_SEQ + row] = (float)bi;
    }
}

// ---------------- launch ------------------------------------------------------
extern "C" void kernel_launch(void* const* d_in, const int* in_sizes, int n_in,
                              void* d_out, int out_size)
{
    const float* x  = (const float*)d_in[0];
    const float* Wk = (const float*)d_in[1];
    const float* bk = (const float*)d_in[2];
    const float* Wv = (const float*)d_in[3];
    const float* bv = (const float*)d_in[4];
    // d_in[5]/d_in[6] (Wq,bq) are dead in the reference (x_q = x@Wv+bv)
    float* out = (float*)d_out;

    static bool attr_done = false;
    if (!attr_done) {
        cudaFuncSetAttribute(gemm_proj_kernel, cudaFuncAttributeMaxDynamicSharedMemorySize, PR_SMEM);
        cudaFuncSetAttribute(gemm_sc_kernel, cudaFuncAttributeMaxDynamicSharedMemorySize, G_SMEM);
        attr_done = true;
    }

    // 1) split x into bf16 hi/lo
    convert_x_kernel<<<8192, 256>>>(x);
    // 2) transpose+split both weights in one launch
    dim3 tg(HALF_K / 32, SIZE_K / 32, 2);
    transpose_split_kernel<<<tg, dim3(32, 8)>>>(Wk, Wv);
    // 3) both projections in ONE launch: 128x256 CTAs, BKC64, 2-stage
    dim3 gproj(N_SEQ / 128, HALF_K / 256, 2);   // 32 x 16 x 2 = 1024 CTAs
    gemm_proj_kernel<<<gproj, 256, PR_SMEM>>>(bk, bv);
    // 4) scores (r16-proven config)
    dim3 gsc(N_SEQ / 128, N_SEQ / 128);         // 32 x 32
    gemm_sc_kernel<<<gsc, 128, G_SMEM>>>();
    // 5) softmax + elementwise V + row max/argmax
    softmax_combine_kernel<<<N_SEQ, 256>>>(out);
}